// round 2
// baseline (speedup 1.0000x reference)
#include <cuda_runtime.h>

// HungarianMatcher cost matrix: C[bs,nq,nt] =
//   5*L1(cxcywh) + 2*focal_class_cost(gathered by tgt_id) - 2*GIoU(xyxy)
//
// Strategy:
//  - prep_class: 2*cost_class table [14400 x 91]  (all transcendental work here)
//  - prep_boxes: xyxy + area for pred (14400) and tgt (1600)
//  - prep_ids:   decode tgt_ids (auto-detect int64 vs int32) -> int table
//  - cost_kernel: block = 800 threads = full 1600-target row (2 tgt/thread in
//    registers), TI=10 query rows per block, class tile in smem, float2 stores.

namespace {
constexpr int BS = 16, NQ = 900, NC = 91, NT = 1600;
constexpr int NROWS = BS * NQ;    // 14400
constexpr int TI = 10;            // query rows per block (14400 % 10 == 0)
constexpr int TPB = NT / 2;       // 800 threads, 2 adjacent targets each
}

__device__ float  g_cls2[NROWS * NC];   // 2 * cost_class
__device__ float4 g_qxyxy[NROWS];
__device__ float  g_qarea[NROWS];
__device__ float4 g_txyxy[NT];
__device__ float  g_tarea[NT];
__device__ int    g_tid[NT];

__global__ void prep_class(const float* __restrict__ logits) {
    int i = blockIdx.x * blockDim.x + threadIdx.x;
    if (i >= NROWS * NC) return;
    float x = logits[i];
    float p = __fdividef(1.0f, 1.0f + __expf(-x));
    float omp = 1.0f - p;
    float pos = 0.25f * omp * omp * (-__logf(p + 1e-8f));
    float neg = 0.75f * p * p * (-__logf(omp + 1e-8f));
    g_cls2[i] = 2.0f * (pos - neg);
}

__global__ void prep_boxes(const float* __restrict__ pred_boxes,
                           const float* __restrict__ tgt_boxes) {
    int i = blockIdx.x * blockDim.x + threadIdx.x;
    if (i < NROWS) {
        float4 b = reinterpret_cast<const float4*>(pred_boxes)[i];
        float4 xy;
        xy.x = b.x - 0.5f * b.z; xy.y = b.y - 0.5f * b.w;
        xy.z = b.x + 0.5f * b.z; xy.w = b.y + 0.5f * b.w;
        g_qxyxy[i] = xy;
        g_qarea[i] = (xy.z - xy.x) * (xy.w - xy.y);
    } else if (i < NROWS + NT) {
        int j = i - NROWS;
        float4 b = reinterpret_cast<const float4*>(tgt_boxes)[j];
        float4 xy;
        xy.x = b.x - 0.5f * b.z; xy.y = b.y - 0.5f * b.w;
        xy.z = b.x + 0.5f * b.z; xy.w = b.y + 0.5f * b.w;
        g_txyxy[j] = xy;
        g_tarea[j] = (xy.z - xy.x) * (xy.w - xy.y);
    }
}

// tgt_ids is int64 in the reference, but jax with x64 disabled materializes
// int32. Detect: for nonneg int64 values < 2^31, every odd int32 word of the
// little-endian view is 0. Probability a genuine int32 id stream has its
// first 64 odd-index values all zero is (1/91)^64 ~ 0. All reads used for
// detection stay within the smaller (int32) buffer size.
__global__ void prep_ids(const int* __restrict__ ids32) {
    int j = blockIdx.x * blockDim.x + threadIdx.x;
    if (j >= NT) return;
    bool is64 = true;
#pragma unroll
    for (int k = 1; k < 128; k += 2)
        is64 &= (ids32[k] == 0);
    g_tid[j] = is64 ? ids32[2 * j] : ids32[j];
}

__device__ __forceinline__ float pair_cost(
    const float4 qxy, const float qa, const float4 qc,
    const float4 txy, const float ta, const float4 tc, const float cls2)
{
    // L1 on cxcywh
    float bb = fabsf(qc.x - tc.x) + fabsf(qc.y - tc.y)
             + fabsf(qc.z - tc.z) + fabsf(qc.w - tc.w);
    // intersection
    float ltx = fmaxf(qxy.x, txy.x);
    float lty = fmaxf(qxy.y, txy.y);
    float rbx = fminf(qxy.z, txy.z);
    float rby = fminf(qxy.w, txy.w);
    float w = fmaxf(rbx - ltx, 0.0f);
    float h = fmaxf(rby - lty, 0.0f);
    float inter = w * h;
    float uni = qa + ta - inter;
    float iou = __fdividef(inter, uni);
    // enclosing box (min <= max guaranteed, no clamp needed)
    float ex = fmaxf(qxy.z, txy.z) - fminf(qxy.x, txy.x);
    float ey = fmaxf(qxy.w, txy.w) - fminf(qxy.y, txy.y);
    float ae = ex * ey;
    float giou = iou - __fdividef(ae - uni, ae);
    // C = 5*bb + 2*cls - 2*giou   (cls2 already carries the factor 2)
    return fmaf(5.0f, bb, cls2) - 2.0f * giou;
}

__global__ void __launch_bounds__(TPB)
cost_kernel(const float* __restrict__ pred_boxes,
            const float* __restrict__ tgt_boxes,
            float* __restrict__ out)
{
    __shared__ float s_cls[TI * NC];   // 910 floats = 3.6 KB
    const int t = threadIdx.x;
    const int r0 = blockIdx.x * TI;

    for (int k = t; k < TI * NC; k += TPB)
        s_cls[k] = g_cls2[r0 * NC + k];

    const int j0 = 2 * t;
    const float4 t0xy = g_txyxy[j0];
    const float4 t1xy = g_txyxy[j0 + 1];
    const float  t0a  = g_tarea[j0];
    const float  t1a  = g_tarea[j0 + 1];
    const float4 t0c  = reinterpret_cast<const float4*>(tgt_boxes)[j0];
    const float4 t1c  = reinterpret_cast<const float4*>(tgt_boxes)[j0 + 1];
    const int id0 = g_tid[j0];
    const int id1 = g_tid[j0 + 1];
    __syncthreads();

    float* orow = out + (size_t)r0 * NT + j0;
    const float4* qc_ptr = reinterpret_cast<const float4*>(pred_boxes) + r0;

#pragma unroll
    for (int q = 0; q < TI; ++q) {
        const float4 qxy = g_qxyxy[r0 + q];
        const float  qa  = g_qarea[r0 + q];
        const float4 qc  = qc_ptr[q];
        float c0 = pair_cost(qxy, qa, qc, t0xy, t0a, t0c, s_cls[q * NC + id0]);
        float c1 = pair_cost(qxy, qa, qc, t1xy, t1a, t1c, s_cls[q * NC + id1]);
        *reinterpret_cast<float2*>(orow + (size_t)q * NT) = make_float2(c0, c1);
    }
}

extern "C" void kernel_launch(void* const* d_in, const int* in_sizes, int n_in,
                              void* d_out, int out_size) {
    const float* logits = (const float*)d_in[0];   // [16,900,91]
    const float* pboxes = (const float*)d_in[1];   // [16,900,4]
    const float* tboxes = (const float*)d_in[2];   // [1600,4]
    const int*   ids    = (const int*)d_in[3];     // [1600] (int32 or int64 view)
    float* out = (float*)d_out;                    // [16,900,1600]

    prep_class<<<(NROWS * NC + 255) / 256, 256>>>(logits);
    prep_boxes<<<(NROWS + NT + 255) / 256, 256>>>(pboxes, tboxes);
    prep_ids<<<(NT + 255) / 256, 256>>>(ids);
    cost_kernel<<<NROWS / TI, TPB>>>(pboxes, tboxes, out);
}

// round 3
// speedup vs baseline: 1.3951x; 1.3951x over previous
#include <cuda_runtime.h>

// HungarianMatcher cost matrix: C[bs,nq,nt] =
//   5*L1(cxcywh) + 2*focal_class_cost(gathered by tgt_id) - 2*GIoU(xyxy)
//
// R3 changes vs R2 (latency/occupancy round):
//  - cost_kernel block: 800 -> 160 threads (5 warps), 2 targets/thread,
//    target dim tiled by grid.y=5. __launch_bounds__(160,8) => >=8 blocks/SM
//    (40 warps, ~62% occ) vs 25 warps before.
//  - query-row data (xyxy, area, cxcywh) staged in smem: LDS broadcast
//    instead of per-iteration global loads on the critical path.
//  - three prep kernels fused into one launch.

namespace {
constexpr int BS = 16, NQ = 900, NC = 91, NT = 1600;
constexpr int NROWS = BS * NQ;     // 14400
constexpr int TI = 10;             // query rows per block (14400 % 10 == 0)
constexpr int TPB = 160;           // 5 warps
constexpr int TGT_PER_BLK = 2 * TPB;  // 320 targets per block; 1600/320 = 5
constexpr int NTILE_T = NT / TGT_PER_BLK;  // 5
}

__device__ float  g_cls2[NROWS * NC];   // 2 * cost_class
__device__ float4 g_qxyxy[NROWS];
__device__ float  g_qarea[NROWS];
__device__ float4 g_txyxy[NT];
__device__ float  g_tarea[NT];
__device__ int    g_tid[NT];

// Single fused prep kernel: class table + box xyxy/areas + id decode.
// tgt_ids is int64 in the reference, but jax with x64 disabled materializes
// int32. Detect: for nonneg int64 values < 2^31, every odd int32 word of the
// little-endian view is 0. All detection reads stay within the int32 size.
__global__ void prep_all(const float* __restrict__ logits,
                         const float* __restrict__ pred_boxes,
                         const float* __restrict__ tgt_boxes,
                         const int*   __restrict__ ids32) {
    int i = blockIdx.x * blockDim.x + threadIdx.x;
    if (i < NROWS * NC) {
        float x = logits[i];
        float p = __fdividef(1.0f, 1.0f + __expf(-x));
        float omp = 1.0f - p;
        float pos = 0.25f * omp * omp * (-__logf(p + 1e-8f));
        float neg = 0.75f * p * p * (-__logf(omp + 1e-8f));
        g_cls2[i] = 2.0f * (pos - neg);
    }
    if (i < NROWS + NT) {
        if (i < NROWS) {
            float4 b = reinterpret_cast<const float4*>(pred_boxes)[i];
            float4 xy;
            xy.x = b.x - 0.5f * b.z; xy.y = b.y - 0.5f * b.w;
            xy.z = b.x + 0.5f * b.z; xy.w = b.y + 0.5f * b.w;
            g_qxyxy[i] = xy;
            g_qarea[i] = (xy.z - xy.x) * (xy.w - xy.y);
        } else {
            int j = i - NROWS;
            float4 b = reinterpret_cast<const float4*>(tgt_boxes)[j];
            float4 xy;
            xy.x = b.x - 0.5f * b.z; xy.y = b.y - 0.5f * b.w;
            xy.z = b.x + 0.5f * b.z; xy.w = b.y + 0.5f * b.w;
            g_txyxy[j] = xy;
            g_tarea[j] = (xy.z - xy.x) * (xy.w - xy.y);
        }
    }
    if (i < NT) {
        bool is64 = true;
#pragma unroll
        for (int k = 1; k < 128; k += 2)
            is64 &= (ids32[k] == 0);
        g_tid[i] = is64 ? ids32[2 * i] : ids32[i];
    }
}

__device__ __forceinline__ float pair_cost(
    const float4 qxy, const float qa, const float4 qc,
    const float4 txy, const float ta, const float4 tc, const float cls2)
{
    // L1 on cxcywh
    float bb = fabsf(qc.x - tc.x) + fabsf(qc.y - tc.y)
             + fabsf(qc.z - tc.z) + fabsf(qc.w - tc.w);
    // intersection
    float ltx = fmaxf(qxy.x, txy.x);
    float lty = fmaxf(qxy.y, txy.y);
    float rbx = fminf(qxy.z, txy.z);
    float rby = fminf(qxy.w, txy.w);
    float w = fmaxf(rbx - ltx, 0.0f);
    float h = fmaxf(rby - lty, 0.0f);
    float inter = w * h;
    float uni = qa + ta - inter;
    float iou = __fdividef(inter, uni);
    // enclosing box (min <= max guaranteed, no clamp needed)
    float ex = fmaxf(qxy.z, txy.z) - fminf(qxy.x, txy.x);
    float ey = fmaxf(qxy.w, txy.w) - fminf(qxy.y, txy.y);
    float ae = ex * ey;
    float giou = iou - __fdividef(ae - uni, ae);
    // C = 5*bb + 2*cls - 2*giou   (cls2 already carries the factor 2)
    return fmaf(5.0f, bb, cls2) - 2.0f * giou;
}

__global__ void __launch_bounds__(TPB, 8)
cost_kernel(const float* __restrict__ pred_boxes,
            const float* __restrict__ tgt_boxes,
            float* __restrict__ out)
{
    __shared__ float  s_cls[TI * NC];   // 910 floats = 3.6 KB
    __shared__ float4 s_qxy[TI];
    __shared__ float4 s_qc[TI];
    __shared__ float  s_qa[TI];

    const int t  = threadIdx.x;
    const int r0 = blockIdx.x * TI;
    const int j0 = blockIdx.y * TGT_PER_BLK + 2 * t;

    for (int k = t; k < TI * NC; k += TPB)
        s_cls[k] = g_cls2[r0 * NC + k];
    if (t < TI) {
        s_qxy[t] = g_qxyxy[r0 + t];
        s_qc[t]  = reinterpret_cast<const float4*>(pred_boxes)[r0 + t];
        s_qa[t]  = g_qarea[r0 + t];
    }

    // per-thread target constants (registers)
    const float4 t0xy = g_txyxy[j0];
    const float4 t1xy = g_txyxy[j0 + 1];
    const float  t0a  = g_tarea[j0];
    const float  t1a  = g_tarea[j0 + 1];
    const float4 t0c  = reinterpret_cast<const float4*>(tgt_boxes)[j0];
    const float4 t1c  = reinterpret_cast<const float4*>(tgt_boxes)[j0 + 1];
    const int id0 = g_tid[j0];
    const int id1 = g_tid[j0 + 1];
    __syncthreads();

    float* orow = out + (size_t)r0 * NT + j0;

#pragma unroll
    for (int q = 0; q < TI; ++q) {
        const float4 qxy = s_qxy[q];
        const float  qa  = s_qa[q];
        const float4 qc  = s_qc[q];
        float c0 = pair_cost(qxy, qa, qc, t0xy, t0a, t0c, s_cls[q * NC + id0]);
        float c1 = pair_cost(qxy, qa, qc, t1xy, t1a, t1c, s_cls[q * NC + id1]);
        *reinterpret_cast<float2*>(orow + (size_t)q * NT) = make_float2(c0, c1);
    }
}

extern "C" void kernel_launch(void* const* d_in, const int* in_sizes, int n_in,
                              void* d_out, int out_size) {
    const float* logits = (const float*)d_in[0];   // [16,900,91]
    const float* pboxes = (const float*)d_in[1];   // [16,900,4]
    const float* tboxes = (const float*)d_in[2];   // [1600,4]
    const int*   ids    = (const int*)d_in[3];     // [1600] (int32 or int64 view)
    float* out = (float*)d_out;                    // [16,900,1600]

    prep_all<<<(NROWS * NC + 255) / 256, 256>>>(logits, pboxes, tboxes, ids);
    dim3 grid(NROWS / TI, NTILE_T);
    cost_kernel<<<grid, TPB>>>(pboxes, tboxes, out);
}

// round 4
// speedup vs baseline: 1.4010x; 1.0042x over previous
#include <cuda_runtime.h>

// HungarianMatcher cost matrix: C[bs,nq,nt] =
//   5*L1(cxcywh) + 2*focal_class_cost(gathered by tgt_id) - 2*GIoU(xyxy)
//
// R3 changes vs R2 (latency/occupancy round):
//  - cost_kernel block: 800 -> 160 threads (5 warps), 2 targets/thread,
//    target dim tiled by grid.y=5. __launch_bounds__(160,8) => >=8 blocks/SM
//    (40 warps, ~62% occ) vs 25 warps before.
//  - query-row data (xyxy, area, cxcywh) staged in smem: LDS broadcast
//    instead of per-iteration global loads on the critical path.
//  - three prep kernels fused into one launch.

namespace {
constexpr int BS = 16, NQ = 900, NC = 91, NT = 1600;
constexpr int NROWS = BS * NQ;     // 14400
constexpr int TI = 10;             // query rows per block (14400 % 10 == 0)
constexpr int TPB = 160;           // 5 warps
constexpr int TGT_PER_BLK = 2 * TPB;  // 320 targets per block; 1600/320 = 5
constexpr int NTILE_T = NT / TGT_PER_BLK;  // 5
}

__device__ float  g_cls2[NROWS * NC];   // 2 * cost_class
__device__ float4 g_qxyxy[NROWS];
__device__ float  g_qarea[NROWS];
__device__ float4 g_txyxy[NT];
__device__ float  g_tarea[NT];
__device__ int    g_tid[NT];

// Single fused prep kernel: class table + box xyxy/areas + id decode.
// tgt_ids is int64 in the reference, but jax with x64 disabled materializes
// int32. Detect: for nonneg int64 values < 2^31, every odd int32 word of the
// little-endian view is 0. All detection reads stay within the int32 size.
__global__ void prep_all(const float* __restrict__ logits,
                         const float* __restrict__ pred_boxes,
                         const float* __restrict__ tgt_boxes,
                         const int*   __restrict__ ids32) {
    int i = blockIdx.x * blockDim.x + threadIdx.x;
    if (i < NROWS * NC) {
        float x = logits[i];
        float p = __fdividef(1.0f, 1.0f + __expf(-x));
        float omp = 1.0f - p;
        float pos = 0.25f * omp * omp * (-__logf(p + 1e-8f));
        float neg = 0.75f * p * p * (-__logf(omp + 1e-8f));
        g_cls2[i] = 2.0f * (pos - neg);
    }
    if (i < NROWS + NT) {
        if (i < NROWS) {
            float4 b = reinterpret_cast<const float4*>(pred_boxes)[i];
            float4 xy;
            xy.x = b.x - 0.5f * b.z; xy.y = b.y - 0.5f * b.w;
            xy.z = b.x + 0.5f * b.z; xy.w = b.y + 0.5f * b.w;
            g_qxyxy[i] = xy;
            g_qarea[i] = (xy.z - xy.x) * (xy.w - xy.y);
        } else {
            int j = i - NROWS;
            float4 b = reinterpret_cast<const float4*>(tgt_boxes)[j];
            float4 xy;
            xy.x = b.x - 0.5f * b.z; xy.y = b.y - 0.5f * b.w;
            xy.z = b.x + 0.5f * b.z; xy.w = b.y + 0.5f * b.w;
            g_txyxy[j] = xy;
            g_tarea[j] = (xy.z - xy.x) * (xy.w - xy.y);
        }
    }
    if (i < NT) {
        bool is64 = true;
#pragma unroll
        for (int k = 1; k < 128; k += 2)
            is64 &= (ids32[k] == 0);
        g_tid[i] = is64 ? ids32[2 * i] : ids32[i];
    }
}

__device__ __forceinline__ float pair_cost(
    const float4 qxy, const float qa, const float4 qc,
    const float4 txy, const float ta, const float4 tc, const float cls2)
{
    // L1 on cxcywh
    float bb = fabsf(qc.x - tc.x) + fabsf(qc.y - tc.y)
             + fabsf(qc.z - tc.z) + fabsf(qc.w - tc.w);
    // intersection
    float ltx = fmaxf(qxy.x, txy.x);
    float lty = fmaxf(qxy.y, txy.y);
    float rbx = fminf(qxy.z, txy.z);
    float rby = fminf(qxy.w, txy.w);
    float w = fmaxf(rbx - ltx, 0.0f);
    float h = fmaxf(rby - lty, 0.0f);
    float inter = w * h;
    float uni = qa + ta - inter;
    float iou = __fdividef(inter, uni);
    // enclosing box (min <= max guaranteed, no clamp needed)
    float ex = fmaxf(qxy.z, txy.z) - fminf(qxy.x, txy.x);
    float ey = fmaxf(qxy.w, txy.w) - fminf(qxy.y, txy.y);
    float ae = ex * ey;
    float giou = iou - __fdividef(ae - uni, ae);
    // C = 5*bb + 2*cls - 2*giou   (cls2 already carries the factor 2)
    return fmaf(5.0f, bb, cls2) - 2.0f * giou;
}

__global__ void __launch_bounds__(TPB, 8)
cost_kernel(const float* __restrict__ pred_boxes,
            const float* __restrict__ tgt_boxes,
            float* __restrict__ out)
{
    __shared__ float  s_cls[TI * NC];   // 910 floats = 3.6 KB
    __shared__ float4 s_qxy[TI];
    __shared__ float4 s_qc[TI];
    __shared__ float  s_qa[TI];

    const int t  = threadIdx.x;
    const int r0 = blockIdx.x * TI;
    const int j0 = blockIdx.y * TGT_PER_BLK + 2 * t;

    for (int k = t; k < TI * NC; k += TPB)
        s_cls[k] = g_cls2[r0 * NC + k];
    if (t < TI) {
        s_qxy[t] = g_qxyxy[r0 + t];
        s_qc[t]  = reinterpret_cast<const float4*>(pred_boxes)[r0 + t];
        s_qa[t]  = g_qarea[r0 + t];
    }

    // per-thread target constants (registers)
    const float4 t0xy = g_txyxy[j0];
    const float4 t1xy = g_txyxy[j0 + 1];
    const float  t0a  = g_tarea[j0];
    const float  t1a  = g_tarea[j0 + 1];
    const float4 t0c  = reinterpret_cast<const float4*>(tgt_boxes)[j0];
    const float4 t1c  = reinterpret_cast<const float4*>(tgt_boxes)[j0 + 1];
    const int id0 = g_tid[j0];
    const int id1 = g_tid[j0 + 1];
    __syncthreads();

    float* orow = out + (size_t)r0 * NT + j0;

#pragma unroll
    for (int q = 0; q < TI; ++q) {
        const float4 qxy = s_qxy[q];
        const float  qa  = s_qa[q];
        const float4 qc  = s_qc[q];
        float c0 = pair_cost(qxy, qa, qc, t0xy, t0a, t0c, s_cls[q * NC + id0]);
        float c1 = pair_cost(qxy, qa, qc, t1xy, t1a, t1c, s_cls[q * NC + id1]);
        *reinterpret_cast<float2*>(orow + (size_t)q * NT) = make_float2(c0, c1);
    }
}

extern "C" void kernel_launch(void* const* d_in, const int* in_sizes, int n_in,
                              void* d_out, int out_size) {
    const float* logits = (const float*)d_in[0];   // [16,900,91]
    const float* pboxes = (const float*)d_in[1];   // [16,900,4]
    const float* tboxes = (const float*)d_in[2];   // [1600,4]
    const int*   ids    = (const int*)d_in[3];     // [1600] (int32 or int64 view)
    float* out = (float*)d_out;                    // [16,900,1600]

    prep_all<<<(NROWS * NC + 255) / 256, 256>>>(logits, pboxes, tboxes, ids);
    dim3 grid(NROWS / TI, NTILE_T);
    cost_kernel<<<grid, TPB>>>(pboxes, tboxes, out);
}